// round 3
// baseline (speedup 1.0000x reference)
#include <cuda_runtime.h>

// ---------------------------------------------------------------------------
// Fused kernel: per-block scalar Sinkhorn (thread 0, ~0.7us, rows/cols have
// 4-way ILP) -> smem broadcast -> grid-stride streaming mix.
//
//   out[bt, n, d] = sum_m H[n,m] * x[bt, m, d]
//   x viewed as [BT=16384][M=4][DV=256 float4]. One "unit" = 2 bt rows.
//   Per thread per unit: 8 front-batched float4 loads (MLP=8), 32 FMAs x4,
//   8 float4 stores. Streaming hints (read-once / write-once, 512MB traffic).
// ---------------------------------------------------------------------------
__global__ __launch_bounds__(256) void fused_mix_kernel(
    const float* __restrict__ H_raw,
    const float4* __restrict__ x,
    float4* __restrict__ out,
    int n_units)
{
    __shared__ float sh[16];

    if (threadIdx.x == 0) {
        float A[16];
        #pragma unroll
        for (int i = 0; i < 16; i++) A[i] = fabsf(H_raw[i]) + 1e-8f;

        #pragma unroll 1
        for (int it = 0; it < 20; it++) {
            // Row normalize (4 independent rows -> ILP)
            #pragma unroll
            for (int i = 0; i < 4; i++) {
                float s = (A[4*i+0] + A[4*i+1]) + (A[4*i+2] + A[4*i+3]);
                float inv = __frcp_rn(s);
                #pragma unroll
                for (int j = 0; j < 4; j++) A[4*i+j] *= inv;
            }
            // Col normalize (4 independent cols -> ILP)
            #pragma unroll
            for (int j = 0; j < 4; j++) {
                float s = (A[0+j] + A[4+j]) + (A[8+j] + A[12+j]);
                float inv = __frcp_rn(s);
                #pragma unroll
                for (int i = 0; i < 4; i++) A[4*i+j] *= inv;
            }
        }
        #pragma unroll
        for (int i = 0; i < 16; i++) sh[i] = A[i];
    }
    __syncthreads();

    // Broadcast H into registers (conflict-free smem broadcast).
    float h[16];
    #pragma unroll
    for (int i = 0; i < 16; i++) h[i] = sh[i];

    const int q = threadIdx.x;

    for (int unit = blockIdx.x; unit < n_units; unit += gridDim.x) {
        const float4* __restrict__ xa = x + (size_t)unit * 2048;  // bt = 2*unit
        const float4* __restrict__ xb = xa + 1024;                 // bt = 2*unit+1
        float4* __restrict__ oa       = out + (size_t)unit * 2048;
        float4* __restrict__ ob       = oa + 1024;

        // Front-batch all 8 stream loads (MLP=8), evict-first.
        float4 a0 = __ldcs(xa + 0 * 256 + q);
        float4 a1 = __ldcs(xa + 1 * 256 + q);
        float4 a2 = __ldcs(xa + 2 * 256 + q);
        float4 a3 = __ldcs(xa + 3 * 256 + q);
        float4 b0 = __ldcs(xb + 0 * 256 + q);
        float4 b1 = __ldcs(xb + 1 * 256 + q);
        float4 b2 = __ldcs(xb + 2 * 256 + q);
        float4 b3 = __ldcs(xb + 3 * 256 + q);

        #pragma unroll
        for (int n = 0; n < 4; n++) {
            const float h0 = h[n * 4 + 0], h1 = h[n * 4 + 1];
            const float h2 = h[n * 4 + 2], h3 = h[n * 4 + 3];
            float4 o;
            o.x = h0 * a0.x + h1 * a1.x + h2 * a2.x + h3 * a3.x;
            o.y = h0 * a0.y + h1 * a1.y + h2 * a2.y + h3 * a3.y;
            o.z = h0 * a0.z + h1 * a1.z + h2 * a2.z + h3 * a3.z;
            o.w = h0 * a0.w + h1 * a1.w + h2 * a2.w + h3 * a3.w;
            __stcs(oa + n * 256 + q, o);
        }
        #pragma unroll
        for (int n = 0; n < 4; n++) {
            const float h0 = h[n * 4 + 0], h1 = h[n * 4 + 1];
            const float h2 = h[n * 4 + 2], h3 = h[n * 4 + 3];
            float4 o;
            o.x = h0 * b0.x + h1 * b1.x + h2 * b2.x + h3 * b3.x;
            o.y = h0 * b0.y + h1 * b1.y + h2 * b2.y + h3 * b3.y;
            o.z = h0 * b0.z + h1 * b1.z + h2 * b2.z + h3 * b3.z;
            o.w = h0 * b0.w + h1 * b1.w + h2 * b2.w + h3 * b3.w;
            __stcs(ob + n * 256 + q, o);
        }
    }
}

extern "C" void kernel_launch(void* const* d_in, const int* in_sizes, int n_in,
                              void* d_out, int out_size) {
    const float* x     = (const float*)d_in[0];  // [4, 4096, 4, 1024] fp32
    const float* H_raw = (const float*)d_in[1];  // [4, 4]
    float* out         = (float*)d_out;          // [4, 4096, 4, 1024] fp32

    const int BT      = 4 * 4096;   // 16384 (b,t) pairs
    const int n_units = BT / 2;     // 8192 two-row units

    // Persistent-ish grid: ~4 blocks/SM on 152 SMs; grid-stride covers rest.
    const int grid = 152 * 4;
    fused_mix_kernel<<<grid, 256>>>(H_raw, (const float4*)x, (float4*)out, n_units);
    (void)in_sizes; (void)n_in; (void)out_size;
}